// round 17
// baseline (speedup 1.0000x reference)
#include <cuda_runtime.h>
#include <cuda_fp16.h>

// ---------------------------------------------------------------------------
// GCN 2-layer via fire-and-forget vector scatter-reduction (red.global.v4.f32).
// No CSR build: each edge REDs its contribution directly into per-node
// accumulators (g_s 8MB, g_o 16MB - both L2-resident). Self-loops folded
// analytically into the per-node kernels.
// ---------------------------------------------------------------------------

#define MAXN 500000

__device__ int    g_cnt[MAXN];        // in-degrees
__device__ uint2  g_xs[MAXN];         // fp16 x4 (3 used): dis*x
__device__ float4 g_s[MAXN];          // layer-1 accumulators (fp32)
__device__ uint4  g_h2s[MAXN];        // fp16 x8 (7 used): dis*(relu(h1)@W2)
__device__ float4 g_o[MAXN * 2];      // layer-2 accumulators (8 fp32, 7 used)
__device__ float  g_wk[192];          // W1(48) b1(16) W2(112) b2(7)

__device__ __forceinline__ void red4(float4* p, float a, float b, float c, float d) {
    asm volatile("red.global.add.v4.f32 [%0], {%1,%2,%3,%4};"
                 :: "l"(p), "f"(a), "f"(b), "f"(c), "f"(d) : "memory");
}

// zero counters + accumulators, stage weights
__global__ void k_init(const float* __restrict__ W1, const float* __restrict__ b1,
                       const float* __restrict__ W2, const float* __restrict__ b2,
                       int n) {
    int i = blockIdx.x * blockDim.x + threadIdx.x;
    if (i < n) {
        g_cnt[i] = 0;
        g_s[i] = make_float4(0.f, 0.f, 0.f, 0.f);
        g_o[2 * i]     = make_float4(0.f, 0.f, 0.f, 0.f);
        g_o[2 * i + 1] = make_float4(0.f, 0.f, 0.f, 0.f);
    }
    if (blockIdx.x == 0) {
        int t = threadIdx.x;
        if (t < 48)       g_wk[t] = W1[t];
        else if (t < 64)  g_wk[t] = b1[t - 48];
        else if (t < 176) g_wk[t] = W2[t - 64];
        else if (t < 183) g_wk[t] = b2[t - 176];
    }
}

// degrees via no-return atomics (RED)
__global__ void k_count(const int* __restrict__ col, int E) {
    int base = (blockIdx.x * blockDim.x + threadIdx.x) * 4;
    if (base + 3 < E) {
        int4 c = *(const int4*)(col + base);
        atomicAdd(&g_cnt[c.x], 1);
        atomicAdd(&g_cnt[c.y], 1);
        atomicAdd(&g_cnt[c.z], 1);
        atomicAdd(&g_cnt[c.w], 1);
    } else {
        for (int e = base; e < E; e++) atomicAdd(&g_cnt[col[e]], 1);
    }
}

// xs = fp16(dis * x); dis = rsqrt(deg+1)
__global__ void k_xs(const float* __restrict__ x, int N) {
    int n = blockIdx.x * blockDim.x + threadIdx.x;
    if (n >= N) return;
    float d = rsqrtf((float)(g_cnt[n] + 1));
    __half2 p0 = __floats2half2_rn(d * x[3 * n + 0], d * x[3 * n + 1]);
    __half2 p1 = __floats2half2_rn(d * x[3 * n + 2], 0.f);
    uint2 pk;
    pk.x = *(unsigned*)&p0;
    pk.y = *(unsigned*)&p1;
    g_xs[n] = pk;
}

// layer-1 edge pass: g_s[col] += xs[row]  (gather 8B + one v4 RED)
__global__ void k_pass1(const int* __restrict__ row,
                        const int* __restrict__ col, int E) {
    int base = (blockIdx.x * blockDim.x + threadIdx.x) * 4;
    if (base + 3 < E) {
        int4 r = *(const int4*)(row + base);
        int4 c = *(const int4*)(col + base);
        uint2 v0 = g_xs[r.x];
        uint2 v1 = g_xs[r.y];
        uint2 v2 = g_xs[r.z];
        uint2 v3 = g_xs[r.w];
#define P1(v, cc) { float2 a = __half22float2(*(__half2*)&v.x); \
                    float2 b = __half22float2(*(__half2*)&v.y); \
                    red4(&g_s[cc], a.x, a.y, b.x, 0.f); }
        P1(v0, c.x); P1(v1, c.y); P1(v2, c.z); P1(v3, c.w);
#undef P1
    } else {
        for (int e = base; e < E; e++) {
            uint2 v = g_xs[row[e]];
            float2 a = __half22float2(*(__half2*)&v.x);
            float2 b = __half22float2(*(__half2*)&v.y);
            red4(&g_s[col[e]], a.x, a.y, b.x, 0.f);
        }
    }
}

// per-node dense: (g_s + self xs) -> W1+b1+relu+W2 -> fp16 h2s
__global__ void k_node(int N) {
    int n = blockIdx.x * blockDim.x + threadIdx.x;
    if (n >= N) return;
    float4 s = g_s[n];
    uint2 sv = g_xs[n];                        // self loop
    float2 sa = __half22float2(*(__half2*)&sv.x);
    float2 sb = __half22float2(*(__half2*)&sv.y);
    float ax = s.x + sa.x, ay = s.y + sa.y, az = s.z + sb.x;
    float dc = rsqrtf((float)(g_cnt[n] + 1));
    float rv[16];
#pragma unroll
    for (int f = 0; f < 16; f++) {
        float v = fmaf(ax, __ldg(&g_wk[f]),
                       fmaf(ay, __ldg(&g_wk[16 + f]), az * __ldg(&g_wk[32 + f])));
        rv[f] = fmaxf(fmaf(dc, v, __ldg(&g_wk[48 + f])), 0.f);
    }
    float o7[7] = {0.f, 0.f, 0.f, 0.f, 0.f, 0.f, 0.f};
#pragma unroll
    for (int f = 0; f < 16; f++) {
#pragma unroll
        for (int j = 0; j < 7; j++)
            o7[j] = fmaf(rv[f], __ldg(&g_wk[64 + f * 7 + j]), o7[j]);
    }
    uint4 pk;
    __half2 h01 = __floats2half2_rn(dc * o7[0], dc * o7[1]);
    __half2 h23 = __floats2half2_rn(dc * o7[2], dc * o7[3]);
    __half2 h45 = __floats2half2_rn(dc * o7[4], dc * o7[5]);
    __half2 h67 = __floats2half2_rn(dc * o7[6], 0.f);
    pk.x = *(unsigned*)&h01;
    pk.y = *(unsigned*)&h23;
    pk.z = *(unsigned*)&h45;
    pk.w = *(unsigned*)&h67;
    g_h2s[n] = pk;
}

// layer-2 edge pass: g_o[col] += h2s[row]  (gather 16B + two v4 REDs)
__global__ void k_pass2(const int* __restrict__ row,
                        const int* __restrict__ col, int E) {
    int base = (blockIdx.x * blockDim.x + threadIdx.x) * 4;
    if (base + 3 < E) {
        int4 r = *(const int4*)(row + base);
        int4 c = *(const int4*)(col + base);
        uint4 v0 = g_h2s[r.x];
        uint4 v1 = g_h2s[r.y];
        uint4 v2 = g_h2s[r.z];
        uint4 v3 = g_h2s[r.w];
#define P2(v, cc) { float2 f01 = __half22float2(*(__half2*)&v.x); \
                    float2 f23 = __half22float2(*(__half2*)&v.y); \
                    float2 f45 = __half22float2(*(__half2*)&v.z); \
                    float2 f67 = __half22float2(*(__half2*)&v.w); \
                    red4(&g_o[2 * (cc)],     f01.x, f01.y, f23.x, f23.y); \
                    red4(&g_o[2 * (cc) + 1], f45.x, f45.y, f67.x, 0.f); }
        P2(v0, c.x); P2(v1, c.y); P2(v2, c.z); P2(v3, c.w);
#undef P2
    } else {
        for (int e = base; e < E; e++) {
            uint4 v = g_h2s[row[e]];
            int cc = col[e];
            float2 f01 = __half22float2(*(__half2*)&v.x);
            float2 f23 = __half22float2(*(__half2*)&v.y);
            float2 f45 = __half22float2(*(__half2*)&v.z);
            red4(&g_o[2 * cc],     f01.x, f01.y, f23.x, f23.y);
            red4(&g_o[2 * cc + 1], f45.x, f45.y, 0.f, 0.f);
        }
    }
}

// per-node output: (g_o + self h2s)*dc + b2, log_softmax
__global__ void k_out(float* __restrict__ out, int N) {
    int n = blockIdx.x * blockDim.x + threadIdx.x;
    if (n >= N) return;
    float4 A = g_o[2 * n];
    float4 B = g_o[2 * n + 1];
    uint4 sv = g_h2s[n];                       // self loop
    float2 s01 = __half22float2(*(__half2*)&sv.x);
    float2 s23 = __half22float2(*(__half2*)&sv.y);
    float2 s45 = __half22float2(*(__half2*)&sv.z);
    float2 s67 = __half22float2(*(__half2*)&sv.w);
    float dc = rsqrtf((float)(g_cnt[n] + 1));
    float o7[7];
    o7[0] = fmaf(dc, A.x + s01.x, __ldg(&g_wk[176]));
    o7[1] = fmaf(dc, A.y + s01.y, __ldg(&g_wk[177]));
    o7[2] = fmaf(dc, A.z + s23.x, __ldg(&g_wk[178]));
    o7[3] = fmaf(dc, A.w + s23.y, __ldg(&g_wk[179]));
    o7[4] = fmaf(dc, B.x + s45.x, __ldg(&g_wk[180]));
    o7[5] = fmaf(dc, B.y + s45.y, __ldg(&g_wk[181]));
    o7[6] = fmaf(dc, B.z + s67.x, __ldg(&g_wk[182]));
    float m = o7[0];
#pragma unroll
    for (int k = 1; k < 7; k++) m = fmaxf(m, o7[k]);
    float sum = 0.f;
#pragma unroll
    for (int k = 0; k < 7; k++) sum += expf(o7[k] - m);
    float l = m + logf(sum);
    float* dst = out + (size_t)n * 7;
#pragma unroll
    for (int k = 0; k < 7; k++) dst[k] = o7[k] - l;
}

// ---------------------------------------------------------------------------

extern "C" void kernel_launch(void* const* d_in, const int* in_sizes, int n_in,
                              void* d_out, int out_size) {
    int N = in_sizes[0] / 3;
    int E = in_sizes[1] / 2;
    const float* x  = (const float*)d_in[0];
    const int*   ei = (const int*)d_in[1];
    const float* W1 = (const float*)d_in[2];
    const float* b1 = (const float*)d_in[3];
    const float* W2 = (const float*)d_in[4];
    const float* b2 = (const float*)d_in[5];
    float* out = (float*)d_out;

    const int* row = ei;
    const int* col = ei + E;
    int e4 = (E + 3) / 4;

    k_init<<<(N + 255) / 256, 256>>>(W1, b1, W2, b2, N);   // 1
    k_count<<<(e4 + 255) / 256, 256>>>(col, E);            // 2
    k_xs<<<(N + 255) / 256, 256>>>(x, N);                  // 3
    k_pass1<<<(e4 + 255) / 256, 256>>>(row, col, E);       // 4 <- ncu slot
    k_node<<<(N + 255) / 256, 256>>>(N);                   // 5
    k_pass2<<<(e4 + 255) / 256, 256>>>(row, col, E);       // 6
    k_out<<<(N + 255) / 256, 256>>>(out, N);               // 7
}